// round 3
// baseline (speedup 1.0000x reference)
#include <cuda_runtime.h>
#include <cuda_bf16.h>
#include <cstdint>

#define N_NODES 100000
#define N_EDGES 1600000
#define D 64

// ---------------- static device scratch (no allocation allowed) -------------
__device__ int   g_deg[N_NODES];        // in-degree (without self loop)
__device__ float g_dinv[N_NODES];       // rsqrt(deg+1)
__device__ int   g_off[N_NODES];        // CSR offsets (contiguous ranges)
__device__ int   g_cnt[N_NODES];        // fill cursors for binning
__device__ int   g_src[N_EDGES];        // CSR-by-dst: source node per slot
__device__ float g_norm[N_EDGES];       // per-edge norm = dinv[src]*dinv[dst]
__device__ float g_h[(size_t)N_NODES * D];   // GEMM output buffer
__device__ float g_t[(size_t)N_NODES * D];   // layer-1 activation buffer
__device__ int   g_cursor;

// ---------------------------------------------------------------------------
__global__ void init_kernel() {
    int i = blockIdx.x * blockDim.x + threadIdx.x;
    if (i == 0) g_cursor = 0;
    if (i < N_NODES) g_deg[i] = 0;
}

// edge_index is int32 (JAX x64 is disabled by default: jnp.int64 -> int32).
__global__ void deg_kernel(const int* __restrict__ ei) {
    int e = blockIdx.x * blockDim.x + threadIdx.x;
    if (e < N_EDGES) {
        int dst = ei[N_EDGES + e];
        atomicAdd(&g_deg[dst], 1);
    }
}

// Reserve contiguous CSR ranges via warp-aggregated atomic; compute dinv; zero cnt.
__global__ void offsets_kernel() {
    int n = blockIdx.x * blockDim.x + threadIdx.x;
    int d = (n < N_NODES) ? g_deg[n] : 0;
    int lane = threadIdx.x & 31;
    // inclusive warp scan of d
    int incl = d;
    #pragma unroll
    for (int o = 1; o < 32; o <<= 1) {
        int v = __shfl_up_sync(0xFFFFFFFFu, incl, o);
        if (lane >= o) incl += v;
    }
    int total = __shfl_sync(0xFFFFFFFFu, incl, 31);
    int base = 0;
    if (lane == 31) base = atomicAdd(&g_cursor, total);
    base = __shfl_sync(0xFFFFFFFFu, base, 31);
    if (n < N_NODES) {
        g_off[n]  = base + (incl - d);   // exclusive prefix within warp
        g_cnt[n]  = 0;
        g_dinv[n] = rsqrtf((float)(d + 1));
    }
}

__global__ void bin_kernel(const int* __restrict__ ei) {
    int e = blockIdx.x * blockDim.x + threadIdx.x;
    if (e < N_EDGES) {
        int s = ei[e];
        int d = ei[N_EDGES + e];
        int p = g_off[d] + atomicAdd(&g_cnt[d], 1);
        g_src[p]  = s;
        g_norm[p] = g_dinv[s] * g_dinv[d];
    }
}

// C[N,64] = A[N,64] @ W[64,64]   (one thread per output row, W staged in smem)
__global__ void gemm_kernel(const float* __restrict__ Ain,  // used if use_gt==0
                            const float* __restrict__ W,
                            int use_gt)                      // 1: A = g_t
{
    __shared__ float4 sW[1024];          // 64 rows x 16 float4
    int t = threadIdx.x;
    const float4* Wv = (const float4*)W;
    #pragma unroll
    for (int r = 0; r < 4; r++) sW[t + 256 * r] = Wv[t + 256 * r];
    __syncthreads();

    int row = blockIdx.x * 256 + t;
    if (row >= N_NODES) return;

    const float* A = use_gt ? (const float*)g_t : Ain;
    const float4* Av = (const float4*)(A + (size_t)row * D);
    float4 acc[16];
    #pragma unroll
    for (int j = 0; j < 16; j++) acc[j] = make_float4(0.f, 0.f, 0.f, 0.f);

    #pragma unroll
    for (int kk = 0; kk < 4; kk++) {
        float4 a4[4];
        #pragma unroll
        for (int i = 0; i < 4; i++) a4[i] = Av[kk * 4 + i];
        #pragma unroll
        for (int ki = 0; ki < 16; ki++) {
            float av = ((const float*)a4)[ki];
            int k = kk * 16 + ki;
            #pragma unroll
            for (int j = 0; j < 16; j++) {
                float4 w = sW[k * 16 + j];
                acc[j].x = fmaf(av, w.x, acc[j].x);
                acc[j].y = fmaf(av, w.y, acc[j].y);
                acc[j].z = fmaf(av, w.z, acc[j].z);
                acc[j].w = fmaf(av, w.w, acc[j].w);
            }
        }
    }
    float4* Cv = (float4*)(g_h + (size_t)row * D);
    #pragma unroll
    for (int j = 0; j < 16; j++) Cv[j] = acc[j];
}

// out[n] = relu( dinv[n]^2 * h[n] + sum_e norm_e * h[src_e] + b )
// 16 threads per node, each owns a float4 column chunk. hin = g_h always.
__global__ void agg_kernel(const float* __restrict__ bias,
                           float* __restrict__ out_ext,  // used if to_gt==0
                           int to_gt)                    // 1: out = g_t
{
    int t = blockIdx.x * 256 + threadIdx.x;
    int n = t >> 4;
    if (n >= N_NODES) return;
    int c = (t & 15) * 4;

    const float* hin = (const float*)g_h;
    float di = g_dinv[n];
    float self_w = di * di;
    float4 hv = *(const float4*)(hin + (size_t)n * D + c);
    float4 acc;
    acc.x = self_w * hv.x; acc.y = self_w * hv.y;
    acc.z = self_w * hv.z; acc.w = self_w * hv.w;

    int s0  = g_off[n];
    int cnt = g_deg[n];
    #pragma unroll 4
    for (int i = 0; i < cnt; i++) {
        int   s = g_src[s0 + i];
        float w = g_norm[s0 + i];
        float4 v = *(const float4*)(hin + (size_t)s * D + c);
        acc.x = fmaf(w, v.x, acc.x);
        acc.y = fmaf(w, v.y, acc.y);
        acc.z = fmaf(w, v.z, acc.z);
        acc.w = fmaf(w, v.w, acc.w);
    }
    float4 b = *(const float4*)(bias + c);
    acc.x = fmaxf(acc.x + b.x, 0.f);
    acc.y = fmaxf(acc.y + b.y, 0.f);
    acc.z = fmaxf(acc.z + b.z, 0.f);
    acc.w = fmaxf(acc.w + b.w, 0.f);

    float* out = to_gt ? (float*)g_t : out_ext;
    *(float4*)(out + (size_t)n * D + c) = acc;
}

// ---------------------------------------------------------------------------
extern "C" void kernel_launch(void* const* d_in, const int* in_sizes, int n_in,
                              void* d_out, int out_size) {
    const float* x  = (const float*)d_in[0];
    const int*   ei = (const int*)d_in[1];     // int32 edge_index (2, E) flattened
    const float* W1 = (const float*)d_in[2];
    const float* b1 = (const float*)d_in[3];
    const float* W2 = (const float*)d_in[4];
    const float* b2 = (const float*)d_in[5];
    float*       out = (float*)d_out;

    const int TB = 256;
    int nodeBlocks = (N_NODES + TB - 1) / TB;          // 391
    int edgeBlocks = (N_EDGES + TB - 1) / TB;          // 6250
    int aggBlocks  = (N_NODES * 16 + TB - 1) / TB;     // 6250
    int gemmBlocks = (N_NODES + TB - 1) / TB;          // 391

    // ---- graph structure (rebuilt every call; deterministic work) ----
    init_kernel<<<nodeBlocks, TB>>>();
    deg_kernel<<<edgeBlocks, TB>>>(ei);
    offsets_kernel<<<nodeBlocks, TB>>>();
    bin_kernel<<<edgeBlocks, TB>>>(ei);

    // ---- layer 1: h = x@W1 ; g_t = relu(agg(h) + b1) ----
    gemm_kernel<<<gemmBlocks, TB>>>(x, W1, 0);
    agg_kernel<<<aggBlocks, TB>>>(b1, nullptr, 1);

    // ---- layer 2: h = g_t@W2 ; out = relu(agg(h) + b2) ----
    gemm_kernel<<<gemmBlocks, TB>>>(nullptr, W2, 1);
    agg_kernel<<<aggBlocks, TB>>>(b2, out, 0);
}

// round 4
// speedup vs baseline: 1.6090x; 1.6090x over previous
#include <cuda_runtime.h>
#include <cuda_bf16.h>
#include <cstdint>

#define N_NODES 100000
#define N_EDGES 1600000
#define D 64

// ---------------- static device scratch (no allocation allowed) -------------
__device__ int   g_deg[N_NODES];        // in-degree (without self loop)
__device__ float g_dinv[N_NODES];       // rsqrt(deg+1)
__device__ int   g_off[N_NODES];        // CSR offsets (contiguous ranges)
__device__ int   g_cnt[N_NODES];        // fill cursors for binning
__device__ int   g_src[N_EDGES];        // CSR-by-dst: source node per slot
__device__ float g_h[(size_t)N_NODES * D];   // scaled GEMM output hs = dinv*h
__device__ float g_t[(size_t)N_NODES * D];   // layer-1 activation buffer
__device__ int   g_cursor;

// ---------------- f32x2 packed-math helpers (Blackwell) ---------------------
__device__ __forceinline__ unsigned long long pack2(float lo, float hi) {
    unsigned long long r;
    asm("mov.b64 %0, {%1, %2};" : "=l"(r)
        : "r"(__float_as_uint(lo)), "r"(__float_as_uint(hi)));
    return r;
}
__device__ __forceinline__ unsigned long long fma2(unsigned long long a,
                                                   unsigned long long b,
                                                   unsigned long long c) {
    unsigned long long d;
    asm("fma.rn.f32x2 %0, %1, %2, %3;" : "=l"(d) : "l"(a), "l"(b), "l"(c));
    return d;
}
__device__ __forceinline__ unsigned long long mul2(unsigned long long a,
                                                   unsigned long long b) {
    unsigned long long d;
    asm("mul.rn.f32x2 %0, %1, %2;" : "=l"(d) : "l"(a), "l"(b));
    return d;
}

// ---------------------------------------------------------------------------
__global__ void init_kernel() {
    int i = blockIdx.x * blockDim.x + threadIdx.x;
    if (i == 0) g_cursor = 0;
    if (i < N_NODES) g_deg[i] = 0;
}

// edge_index is int32. 4 edges per thread, vectorized load, REDG (no return).
__global__ void deg_kernel(const int* __restrict__ ei) {
    int e4 = blockIdx.x * blockDim.x + threadIdx.x;
    if (e4 * 4 < N_EDGES) {
        int4 d4 = *(const int4*)(ei + N_EDGES + e4 * 4);
        atomicAdd(&g_deg[d4.x], 1);
        atomicAdd(&g_deg[d4.y], 1);
        atomicAdd(&g_deg[d4.z], 1);
        atomicAdd(&g_deg[d4.w], 1);
    }
}

// Reserve contiguous CSR ranges via warp-aggregated atomic; compute dinv; zero cnt.
__global__ void offsets_kernel() {
    int n = blockIdx.x * blockDim.x + threadIdx.x;
    int d = (n < N_NODES) ? g_deg[n] : 0;
    int lane = threadIdx.x & 31;
    int incl = d;
    #pragma unroll
    for (int o = 1; o < 32; o <<= 1) {
        int v = __shfl_up_sync(0xFFFFFFFFu, incl, o);
        if (lane >= o) incl += v;
    }
    int total = __shfl_sync(0xFFFFFFFFu, incl, 31);
    int base = 0;
    if (lane == 31) base = atomicAdd(&g_cursor, total);
    base = __shfl_sync(0xFFFFFFFFu, base, 31);
    if (n < N_NODES) {
        g_off[n]  = base + (incl - d);
        g_cnt[n]  = 0;
        g_dinv[n] = rsqrtf((float)(d + 1));
    }
}

// Minimal binning: one atomic + one scattered 4B store per edge. No norms.
__global__ void bin_kernel(const int* __restrict__ ei) {
    int e = blockIdx.x * blockDim.x + threadIdx.x;
    if (e < N_EDGES) {
        int s = ei[e];
        int d = ei[N_EDGES + e];
        int p = g_off[d] + atomicAdd(&g_cnt[d], 1);
        g_src[p] = s;
    }
}

// g_h[row] = dinv[row] * (A[row] @ W)   — packed f32x2 FMA inner loop.
__global__ void gemm_kernel(const float* __restrict__ Ain,  // used if use_gt==0
                            const float* __restrict__ W,
                            int use_gt)                      // 1: A = g_t
{
    __shared__ float4 sW[1024];          // 64 rows x 16 float4
    int t = threadIdx.x;
    const float4* Wv = (const float4*)W;
    #pragma unroll
    for (int r = 0; r < 4; r++) sW[t + 256 * r] = Wv[t + 256 * r];
    __syncthreads();

    int row = blockIdx.x * 256 + t;
    if (row >= N_NODES) return;

    const float* A = use_gt ? (const float*)g_t : Ain;
    const float4* Av = (const float4*)(A + (size_t)row * D);

    unsigned long long acc[32];          // 64 fp32 accumulators as 32 f32x2
    #pragma unroll
    for (int j = 0; j < 32; j++) acc[j] = 0ull;

    #pragma unroll
    for (int kk = 0; kk < 4; kk++) {
        float4 a4[4];
        #pragma unroll
        for (int i = 0; i < 4; i++) a4[i] = Av[kk * 4 + i];
        #pragma unroll
        for (int ki = 0; ki < 16; ki++) {
            float av = ((const float*)a4)[ki];
            unsigned long long ap = pack2(av, av);
            int k = kk * 16 + ki;
            #pragma unroll
            for (int j = 0; j < 16; j++) {
                union { float4 f; unsigned long long u[2]; } w;
                w.f = sW[k * 16 + j];
                acc[j * 2 + 0] = fma2(ap, w.u[0], acc[j * 2 + 0]);
                acc[j * 2 + 1] = fma2(ap, w.u[1], acc[j * 2 + 1]);
            }
        }
    }

    float dinv = g_dinv[row];
    unsigned long long dp = pack2(dinv, dinv);
    float4* Cv = (float4*)(g_h + (size_t)row * D);
    #pragma unroll
    for (int j = 0; j < 16; j++) {
        union { float4 f; unsigned long long u[2]; } o;
        o.u[0] = mul2(acc[j * 2 + 0], dp);
        o.u[1] = mul2(acc[j * 2 + 1], dp);
        Cv[j] = o.f;
    }
}

// out[n] = relu( dinv[n] * ( hs[n] + sum_e hs[src_e] ) + b )
// 16 threads per node, each owns a float4 column chunk. hs = g_h.
__global__ void agg_kernel(const float* __restrict__ bias,
                           float* __restrict__ out_ext,  // used if to_gt==0
                           int to_gt)                    // 1: out = g_t
{
    int t = blockIdx.x * 256 + threadIdx.x;
    int n = t >> 4;
    if (n >= N_NODES) return;
    int c = (t & 15) * 4;

    const float* hs = (const float*)g_h;
    float4 acc = *(const float4*)(hs + (size_t)n * D + c);   // self term (pre-scaled)

    int s0  = g_off[n];
    int cnt = g_deg[n];
    #pragma unroll 4
    for (int i = 0; i < cnt; i++) {
        int s = g_src[s0 + i];                                // broadcast within node group
        float4 v = *(const float4*)(hs + (size_t)s * D + c);  // coalesced 256B row gather
        acc.x += v.x; acc.y += v.y; acc.z += v.z; acc.w += v.w;
    }

    float dinv = g_dinv[n];
    float4 b = *(const float4*)(bias + c);
    acc.x = fmaxf(fmaf(dinv, acc.x, b.x), 0.f);
    acc.y = fmaxf(fmaf(dinv, acc.y, b.y), 0.f);
    acc.z = fmaxf(fmaf(dinv, acc.z, b.z), 0.f);
    acc.w = fmaxf(fmaf(dinv, acc.w, b.w), 0.f);

    float* out = to_gt ? (float*)g_t : out_ext;
    *(float4*)(out + (size_t)n * D + c) = acc;
}

// ---------------------------------------------------------------------------
extern "C" void kernel_launch(void* const* d_in, const int* in_sizes, int n_in,
                              void* d_out, int out_size) {
    const float* x  = (const float*)d_in[0];
    const int*   ei = (const int*)d_in[1];     // int32 edge_index (2, E) flattened
    const float* W1 = (const float*)d_in[2];
    const float* b1 = (const float*)d_in[3];
    const float* W2 = (const float*)d_in[4];
    const float* b2 = (const float*)d_in[5];
    float*       out = (float*)d_out;

    const int TB = 256;
    int nodeBlocks = (N_NODES + TB - 1) / TB;              // 391
    int edgeBlocks = (N_EDGES + TB - 1) / TB;              // 6250
    int deg4Blocks = (N_EDGES / 4 + TB - 1) / TB;          // 1563
    int aggBlocks  = (N_NODES * 16 + TB - 1) / TB;         // 6250
    int gemmBlocks = (N_NODES + TB - 1) / TB;              // 391

    // ---- graph structure (rebuilt every call; deterministic work) ----
    init_kernel<<<nodeBlocks, TB>>>();
    deg_kernel<<<deg4Blocks, TB>>>(ei);
    offsets_kernel<<<nodeBlocks, TB>>>();
    bin_kernel<<<edgeBlocks, TB>>>(ei);

    // ---- layer 1: hs = dinv*(x@W1) ; g_t = relu(dinv*(hs[n]+sum hs[src]) + b1) ----
    gemm_kernel<<<gemmBlocks, TB>>>(x, W1, 0);
    agg_kernel<<<aggBlocks, TB>>>(b1, nullptr, 1);

    // ---- layer 2 ----
    gemm_kernel<<<gemmBlocks, TB>>>(nullptr, W2, 1);
    agg_kernel<<<aggBlocks, TB>>>(b2, out, 0);
}

// round 5
// speedup vs baseline: 1.8456x; 1.1470x over previous
#include <cuda_runtime.h>
#include <cuda_fp16.h>
#include <cuda_bf16.h>
#include <cstdint>

#define N_NODES 100000
#define N_EDGES 1600000
#define D 64

// ---------------- static device scratch (no allocation allowed) -------------
__device__ int    g_deg[N_NODES];       // in-degree (without self loop)
__device__ float  g_dinv[N_NODES];      // rsqrt(deg+1)
__device__ int    g_off[N_NODES];       // CSR offsets (contiguous ranges)
__device__ int    g_cnt[N_NODES];       // fill cursors for binning
__device__ int    g_src[N_EDGES];       // CSR-by-dst: source node per slot
__device__ __half g_h[(size_t)N_NODES * D];  // scaled GEMM output hs = dinv*h, fp16
__device__ float  g_t[(size_t)N_NODES * D];  // layer-1 activation buffer (fp32)
__device__ int    g_cursor;

// ---------------- f32x2 packed-math helpers (Blackwell) ---------------------
__device__ __forceinline__ unsigned long long pack2(float lo, float hi) {
    unsigned long long r;
    asm("mov.b64 %0, {%1, %2};" : "=l"(r)
        : "r"(__float_as_uint(lo)), "r"(__float_as_uint(hi)));
    return r;
}
__device__ __forceinline__ unsigned long long fma2(unsigned long long a,
                                                   unsigned long long b,
                                                   unsigned long long c) {
    unsigned long long d;
    asm("fma.rn.f32x2 %0, %1, %2, %3;" : "=l"(d) : "l"(a), "l"(b), "l"(c));
    return d;
}
__device__ __forceinline__ unsigned long long mul2(unsigned long long a,
                                                   unsigned long long b) {
    unsigned long long d;
    asm("mul.rn.f32x2 %0, %1, %2;" : "=l"(d) : "l"(a), "l"(b));
    return d;
}
__device__ __forceinline__ float2 unpack2(unsigned long long v) {
    float2 f;
    unsigned lo, hi;
    asm("mov.b64 {%0, %1}, %2;" : "=r"(lo), "=r"(hi) : "l"(v));
    f.x = __uint_as_float(lo); f.y = __uint_as_float(hi);
    return f;
}

// ---------------------------------------------------------------------------
__global__ void init_kernel() {
    int i = blockIdx.x * blockDim.x + threadIdx.x;
    if (i == 0) g_cursor = 0;
    if (i < N_NODES) g_deg[i] = 0;
}

// edge_index is int32. 4 edges per thread, vectorized load, no-return atomics.
__global__ void deg_kernel(const int* __restrict__ ei) {
    int e4 = blockIdx.x * blockDim.x + threadIdx.x;
    if (e4 * 4 < N_EDGES) {
        int4 d4 = *(const int4*)(ei + N_EDGES + e4 * 4);
        atomicAdd(&g_deg[d4.x], 1);
        atomicAdd(&g_deg[d4.y], 1);
        atomicAdd(&g_deg[d4.z], 1);
        atomicAdd(&g_deg[d4.w], 1);
    }
}

// Reserve contiguous CSR ranges via warp-aggregated atomic; compute dinv; zero cnt.
__global__ void offsets_kernel() {
    int n = blockIdx.x * blockDim.x + threadIdx.x;
    int d = (n < N_NODES) ? g_deg[n] : 0;
    int lane = threadIdx.x & 31;
    int incl = d;
    #pragma unroll
    for (int o = 1; o < 32; o <<= 1) {
        int v = __shfl_up_sync(0xFFFFFFFFu, incl, o);
        if (lane >= o) incl += v;
    }
    int total = __shfl_sync(0xFFFFFFFFu, incl, 31);
    int base = 0;
    if (lane == 31) base = atomicAdd(&g_cursor, total);
    base = __shfl_sync(0xFFFFFFFFu, base, 31);
    if (n < N_NODES) {
        g_off[n]  = base + (incl - d);
        g_cnt[n]  = 0;
        g_dinv[n] = rsqrtf((float)(d + 1));
    }
}

// Minimal binning: one atomic + one scattered 4B store per edge. 2 edges/thread.
__global__ void bin_kernel(const int* __restrict__ ei) {
    int e2 = blockIdx.x * blockDim.x + threadIdx.x;
    if (e2 * 2 < N_EDGES) {
        int2 s2 = *(const int2*)(ei + e2 * 2);
        int2 d2 = *(const int2*)(ei + N_EDGES + e2 * 2);
        int p0 = g_off[d2.x] + atomicAdd(&g_cnt[d2.x], 1);
        g_src[p0] = s2.x;
        int p1 = g_off[d2.y] + atomicAdd(&g_cnt[d2.y], 1);
        g_src[p1] = s2.y;
    }
}

// g_h[row] = half( dinv[row] * (A[row] @ W) )  — packed f32x2 FMA inner loop.
__global__ void gemm_kernel(const float* __restrict__ Ain,  // used if use_gt==0
                            const float* __restrict__ W,
                            int use_gt)                      // 1: A = g_t
{
    __shared__ float4 sW[1024];          // 64 rows x 16 float4
    int t = threadIdx.x;
    const float4* Wv = (const float4*)W;
    #pragma unroll
    for (int r = 0; r < 4; r++) sW[t + 256 * r] = Wv[t + 256 * r];
    __syncthreads();

    int row = blockIdx.x * 256 + t;
    if (row >= N_NODES) return;

    const float* A = use_gt ? (const float*)g_t : Ain;
    const float4* Av = (const float4*)(A + (size_t)row * D);

    unsigned long long acc[32];          // 64 fp32 accumulators as 32 f32x2
    #pragma unroll
    for (int j = 0; j < 32; j++) acc[j] = 0ull;

    #pragma unroll
    for (int kk = 0; kk < 4; kk++) {
        float4 a4[4];
        #pragma unroll
        for (int i = 0; i < 4; i++) a4[i] = Av[kk * 4 + i];
        #pragma unroll
        for (int ki = 0; ki < 16; ki++) {
            float av = ((const float*)a4)[ki];
            unsigned long long ap = pack2(av, av);
            int k = kk * 16 + ki;
            #pragma unroll
            for (int j = 0; j < 16; j++) {
                union { float4 f; unsigned long long u[2]; } w;
                w.f = sW[k * 16 + j];
                acc[j * 2 + 0] = fma2(ap, w.u[0], acc[j * 2 + 0]);
                acc[j * 2 + 1] = fma2(ap, w.u[1], acc[j * 2 + 1]);
            }
        }
    }

    float dinv = g_dinv[row];
    unsigned long long dp = pack2(dinv, dinv);
    // convert 64 fp32 -> 64 fp16, write as 8 x uint4 (16B each)
    uint4* Cv = (uint4*)(g_h + (size_t)row * D);
    #pragma unroll
    for (int j = 0; j < 8; j++) {
        union { uint4 v; __half2 h2[8]; } o;
        #pragma unroll
        for (int q = 0; q < 4; q++) {
            float2 f = unpack2(mul2(acc[j * 4 + q], dp));
            o.h2[q] = __float22half2_rn(f);
        }
        Cv[j] = o.v;
    }
}

// out[n] = relu( dinv[n] * ( hs[n] + sum_e hs[src_e] ) + b )   (hs in fp16)
// 8 threads per node, each owns 8 half columns (16B). Accumulate fp32.
__global__ void agg_kernel(const float* __restrict__ bias,
                           float* __restrict__ out_ext,  // used if to_gt==0
                           int to_gt)                    // 1: out = g_t
{
    int t = blockIdx.x * 256 + threadIdx.x;
    int n = t >> 3;
    if (n >= N_NODES) return;
    int c = (t & 7) * 8;                 // half-column offset

    const __half* hs = (const __half*)g_h;

    union { uint4 v; __half2 h2[8]; } u;
    u.v = *(const uint4*)(hs + (size_t)n * D + c);    // self term (pre-scaled)
    float2 acc[4];
    #pragma unroll
    for (int j = 0; j < 4; j++) acc[j] = __half22float2(u.h2[j]);

    int s0  = g_off[n];
    int cnt = g_deg[n];
    #pragma unroll 4
    for (int i = 0; i < cnt; i++) {
        int s = g_src[s0 + i];
        union { uint4 v; __half2 h2[8]; } w;
        w.v = *(const uint4*)(hs + (size_t)s * D + c);  // coalesced 128B row gather
        #pragma unroll
        for (int j = 0; j < 4; j++) {
            float2 f = __half22float2(w.h2[j]);
            acc[j].x += f.x; acc[j].y += f.y;
        }
    }

    float dinv = g_dinv[n];
    float4 b0 = *(const float4*)(bias + c);
    float4 b1 = *(const float4*)(bias + c + 4);
    float4 o0, o1;
    o0.x = fmaxf(fmaf(dinv, acc[0].x, b0.x), 0.f);
    o0.y = fmaxf(fmaf(dinv, acc[0].y, b0.y), 0.f);
    o0.z = fmaxf(fmaf(dinv, acc[1].x, b0.z), 0.f);
    o0.w = fmaxf(fmaf(dinv, acc[1].y, b0.w), 0.f);
    o1.x = fmaxf(fmaf(dinv, acc[2].x, b1.x), 0.f);
    o1.y = fmaxf(fmaf(dinv, acc[2].y, b1.y), 0.f);
    o1.z = fmaxf(fmaf(dinv, acc[3].x, b1.z), 0.f);
    o1.w = fmaxf(fmaf(dinv, acc[3].y, b1.w), 0.f);

    float* out = to_gt ? (float*)g_t : out_ext;
    *(float4*)(out + (size_t)n * D + c)     = o0;
    *(float4*)(out + (size_t)n * D + c + 4) = o1;
}

// ---------------------------------------------------------------------------
extern "C" void kernel_launch(void* const* d_in, const int* in_sizes, int n_in,
                              void* d_out, int out_size) {
    const float* x  = (const float*)d_in[0];
    const int*   ei = (const int*)d_in[1];     // int32 edge_index (2, E) flattened
    const float* W1 = (const float*)d_in[2];
    const float* b1 = (const float*)d_in[3];
    const float* W2 = (const float*)d_in[4];
    const float* b2 = (const float*)d_in[5];
    float*       out = (float*)d_out;

    const int TB = 256;
    int nodeBlocks = (N_NODES + TB - 1) / TB;              // 391
    int deg4Blocks = (N_EDGES / 4 + TB - 1) / TB;          // 1563
    int bin2Blocks = (N_EDGES / 2 + TB - 1) / TB;          // 3125
    int aggBlocks  = (N_NODES * 8 + TB - 1) / TB;          // 3125
    int gemmBlocks = (N_NODES + TB - 1) / TB;              // 391

    // ---- graph structure (rebuilt every call; deterministic work) ----
    init_kernel<<<nodeBlocks, TB>>>();
    deg_kernel<<<deg4Blocks, TB>>>(ei);
    offsets_kernel<<<nodeBlocks, TB>>>();
    bin_kernel<<<bin2Blocks, TB>>>(ei);

    // ---- layer 1: hs = fp16(dinv*(x@W1)) ; g_t = relu(dinv*(hs[n]+sum hs[src]) + b1) ----
    gemm_kernel<<<gemmBlocks, TB>>>(x, W1, 0);
    agg_kernel<<<aggBlocks, TB>>>(b1, nullptr, 1);

    // ---- layer 2 ----
    gemm_kernel<<<gemmBlocks, TB>>>(nullptr, W2, 1);
    agg_kernel<<<aggBlocks, TB>>>(b2, out, 0);
}